// round 1
// baseline (speedup 1.0000x reference)
#include <cuda_runtime.h>

// ----------------------------------------------------------------------------
// BoxCrossCategoryLoss on GB300.
//
// Each element i gets a triple T = cx*64+cy*8+cz (cx,cy,cz in 0..7).
// POS recipe: 14 distinct triples -> term v1[i,f1]+v2[i,f2]-v3[i,f3],
//             f1=cx>>2, f2=cy>>2, f3=cz>>2 (valid because mask forces equality).
// NEG recipe: 22 distinct triples -> needs index of 1st and 2nd occurrence
//             (argmax-on-empty => index 0), count>0 gate.
// loss = -(sum_pos_terms + sum_neg_terms)
// ----------------------------------------------------------------------------

#define NPOS 14
#define NNEG 22

// Precomputed triple codes T = xy*64 + yz*8 + xz for each recipe entry.
__constant__ int c_pos[NPOS] = {36,52,109,117,164,173,182,191,260,276,333,341,406,471};
__constant__ int c_neg[NNEG] = {33,34,49,50,104,106,112,114,161,162,168,170,
                                257,258,273,274,328,330,336,338,186,466};

#define MAX_PARTIALS 16384
__device__ float               g_partials[MAX_PARTIALS];
__device__ unsigned long long  g_pair[512];   // per-triple packed (min1<<32)|min2
__device__ unsigned char       g_lut[512];    // 0=none, 1=pos, 2=neg

// cls map: idx = r0*2+r1 : (1,0)->0 (0,1)->1 (1,1)->2 (0,0)->3
// packed 2-bit LUT: idx0->3, idx1->1, idx2->0, idx3->2  => 0x87
__device__ __forceinline__ int code_of(int r0, int r1, int fl) {
    int idx = (r0 << 1) | r1;
    return ((0x87 >> (idx * 2)) & 3) + (fl << 2);
}

// Insert index i into the two-smallest set at *p. Indices are unique.
__device__ __forceinline__ void insert2(unsigned long long* p, unsigned i) {
    unsigned long long cur = __ldcg(p);
    while (true) {
        unsigned m1 = (unsigned)(cur >> 32);
        unsigned m2 = (unsigned)cur;
        unsigned long long nv;
        if (i < m1)       nv = ((unsigned long long)i  << 32) | (unsigned long long)m1;
        else if (i < m2)  nv = ((unsigned long long)m1 << 32) | (unsigned long long)i;
        else return;  // stale read only over-estimates minima -> skip is safe
        unsigned long long prev = atomicCAS(p, cur, nv);
        if (prev == cur) return;
        cur = prev;
    }
}

__global__ void init_kernel() {
    int t = threadIdx.x;
    g_pair[t] = 0xFFFFFFFFFFFFFFFFULL;
    g_lut[t]  = 0;
    __syncthreads();
    if (t < NPOS)              g_lut[c_pos[t]] = 1;
    else if (t < NPOS + NNEG)  g_lut[c_neg[t - NPOS]] = 2;
}

__global__ void __launch_bounds__(256)
pass1_kernel(const int4* __restrict__ xy, const int4* __restrict__ yz,
             const int4* __restrict__ xz, const int4* __restrict__ flag4,
             const float* __restrict__ v1, const float* __restrict__ v2,
             const float* __restrict__ v3, int n4) {
    float acc = 0.0f;

    for (int j = blockIdx.x * blockDim.x + threadIdx.x; j < n4;
         j += gridDim.x * blockDim.x) {
        int4 fl = flag4[j];                       // flags for elems 4j..4j+3
        int4 a0 = xy[2 * j], a1 = xy[2 * j + 1];  // (r0,r1) pairs
        int4 b0 = yz[2 * j], b1 = yz[2 * j + 1];
        int4 c0 = xz[2 * j], c1 = xz[2 * j + 1];

        int base = 4 * j;

#define DO_ELEM(K, AX, AY, BX, BY, CX_, CY_, FK)                               \
        {                                                                      \
            int i  = base + (K);                                               \
            int cx = code_of((AX), (AY), (FK));                                \
            int cy = code_of((BX), (BY), (FK));                                \
            int cz = code_of((CX_), (CY_), (FK));                              \
            int T  = (cx << 6) | (cy << 3) | cz;                               \
            unsigned char tag = g_lut[T];                                      \
            if (tag == 1) {                                                    \
                int f1 = T >> 8, f2 = (T >> 5) & 1, f3 = (T >> 2) & 1;         \
                acc += v1[2 * i + f1] + v2[2 * i + f2] - v3[2 * i + f3];       \
            } else if (tag == 2) {                                             \
                insert2(&g_pair[T], (unsigned)i);                              \
            }                                                                  \
        }

        DO_ELEM(0, a0.x, a0.y, b0.x, b0.y, c0.x, c0.y, fl.x)
        DO_ELEM(1, a0.z, a0.w, b0.z, b0.w, c0.z, c0.w, fl.y)
        DO_ELEM(2, a1.x, a1.y, b1.x, b1.y, c1.x, c1.y, fl.z)
        DO_ELEM(3, a1.z, a1.w, b1.z, b1.w, c1.z, c1.w, fl.w)
#undef DO_ELEM
    }

    // block reduction (deterministic within block)
    __shared__ float sh[256];
    int t = threadIdx.x;
    sh[t] = acc;
    __syncthreads();
    for (int o = 128; o > 0; o >>= 1) {
        if (t < o) sh[t] += sh[t + o];
        __syncthreads();
    }
    if (t == 0) g_partials[blockIdx.x] = sh[0];
}

__device__ __forceinline__ float log1mexp_f(float x) {
    const float LOG_HALF = -0.6931471805599453f;
    return (x > LOG_HALF) ? logf(-expm1f(x)) : log1pf(-expf(x));
}

__global__ void __launch_bounds__(256)
finalize_kernel(const float* __restrict__ v1, const float* __restrict__ v2,
                const float* __restrict__ v3, float* __restrict__ out,
                int nPartials) {
    __shared__ float sh[256];
    __shared__ float negsh[32];
    int t = threadIdx.x;

    float s = 0.0f;
    for (int i = t; i < nPartials; i += 256) s += g_partials[i];
    sh[t] = s;
    __syncthreads();
    for (int o = 128; o > 0; o >>= 1) {
        if (t < o) sh[t] += sh[t + o];
        __syncthreads();
    }
    float posSum = sh[0];

    if (t < 32) negsh[t] = 0.0f;
    __syncthreads();

    if (t < NNEG) {
        int T = c_neg[t];
        unsigned long long pr = g_pair[T];
        unsigned m1 = (unsigned)(pr >> 32);
        unsigned m2 = (unsigned)pr;
        float term = 0.0f;
        if (m1 != 0xFFFFFFFFu) {  // count > 0
            unsigned second = (m2 != 0xFFFFFFFFu) ? m2 : 0u;  // argmax-on-empty -> 0
            int f1 = T >> 8, f2 = (T >> 5) & 1, f3 = (T >> 2) & 1;
            unsigned i1 = f1 ? second : m1;
            unsigned i2 = f2 ? second : m1;
            unsigned i3 = f3 ? second : m1;
            term = v1[2 * i1] + v1[2 * i1 + 1]
                 + v2[2 * i2] + v2[2 * i2 + 1]
                 - log1mexp_f(v3[2 * i3]) - log1mexp_f(v3[2 * i3 + 1]);
        }
        negsh[t] = term;
    }
    __syncthreads();

    if (t == 0) {
        float ns = 0.0f;
        for (int k = 0; k < NNEG; k++) ns += negsh[k];
        out[0] = -(posSum + ns);
    }
}

extern "C" void kernel_launch(void* const* d_in, const int* in_sizes, int n_in,
                              void* d_out, int out_size) {
    const float* v1 = (const float*)d_in[0];
    const float* v2 = (const float*)d_in[1];
    const float* v3 = (const float*)d_in[2];
    const int4*  xy = (const int4*)d_in[3];
    const int4*  yz = (const int4*)d_in[4];
    const int4*  xz = (const int4*)d_in[5];
    const int4*  fl = (const int4*)d_in[6];

    int n  = in_sizes[6];      // B (flag element count)
    int n4 = n >> 2;           // B divisible by 4

    int threads = 256;
    int blocks  = (n4 + threads - 1) / threads;
    if (blocks > MAX_PARTIALS) blocks = MAX_PARTIALS;
    if (blocks < 1) blocks = 1;

    init_kernel<<<1, 512>>>();
    pass1_kernel<<<blocks, threads>>>(xy, yz, xz, fl, v1, v2, v3, n4);
    finalize_kernel<<<1, 256>>>(v1, v2, v3, (float*)d_out, blocks);
}